// round 2
// baseline (speedup 1.0000x reference)
#include <cuda_runtime.h>
#include <math.h>

#define BATCH 4
#define TSEQ  1705
#define CEMB  768
#define NHEAD 12
#define HDIM  64
#define MROWS (BATCH*TSEQ)          /* 6820 */
#define KTILES ((TSEQ+63)/64)       /* 27   */

// Scratch (static device arrays — no runtime allocation)
__device__ float g_q[(size_t)BATCH*NHEAD*TSEQ*HDIM];
__device__ float g_k[(size_t)BATCH*NHEAD*TSEQ*HDIM];
__device__ float g_v[(size_t)BATCH*NHEAD*TSEQ*HDIM];
__device__ float g_y[(size_t)MROWS*CEMB];
__device__ unsigned char g_mask[(size_t)TSEQ*TSEQ];

// ---------------------------------------------------------------------------
// Mask normalization: sniff storage dtype on-device, write canonical uint8.
// Guaranteed by construction: mask[0,0]=1, mask[0,1]=1, mask[0,2]=0.
//   uint8/bool storage: bytes [1,1,0,...]
//   int32 storage:      bytes [1,0,0,0, 1,0,0,0, ...]
//   float32 storage:    bytes [0,0,0x80,0x3f, ...]
// ---------------------------------------------------------------------------
__global__ void mask_convert(const unsigned char* __restrict__ raw) {
    size_t i = (size_t)blockIdx.x * blockDim.x + threadIdx.x;
    if (i >= (size_t)TSEQ * TSEQ) return;
    unsigned char b0 = raw[0], b1 = raw[1];
    unsigned char v;
    if (b1 == 1) {                       // uint8 / bool
        v = raw[i] ? 1 : 0;
    } else if (b0 == 1) {                // int32
        v = ((const int*)raw)[i] != 0;
    } else {                             // float32
        v = ((const float*)raw)[i] != 0.0f;
    }
    g_mask[i] = v;
}

// ---------------------------------------------------------------------------
// QKV GEMM: [6820 x 768] @ [768 x 2304] -> scatter into g_q/g_k/g_v [B,H,T,64]
// 128x128 tile, BK=8, 256 threads, 8x8 micro-tile.
// ---------------------------------------------------------------------------
__global__ __launch_bounds__(256) void qkv_gemm(const float* __restrict__ A,
                                                const float* __restrict__ W) {
    __shared__ __align__(16) float As[8][136];   // [k][m] transposed
    __shared__ __align__(16) float Bs[8][136];   // [k][n]
    const int m0 = blockIdx.y * 128;
    const int n0 = blockIdx.x * 128;
    const int tid = threadIdx.x;
    const int ty = tid >> 4;          // 0..15
    const int tx = tid & 15;          // 0..15

    float acc[8][8];
#pragma unroll
    for (int i = 0; i < 8; i++)
#pragma unroll
        for (int j = 0; j < 8; j++) acc[i][j] = 0.f;

    const int arow = tid >> 1;        // 0..127
    const int akc  = (tid & 1) * 4;   // 0 or 4
    const int brow = tid >> 5;        // 0..7
    const int bcol = (tid & 31) * 4;  // 0..124
    const int am   = m0 + arow;

    for (int k0 = 0; k0 < CEMB; k0 += 8) {
        float4 av = make_float4(0.f, 0.f, 0.f, 0.f);
        if (am < MROWS)
            av = *(const float4*)&A[(size_t)am * CEMB + k0 + akc];
        As[akc + 0][arow] = av.x; As[akc + 1][arow] = av.y;
        As[akc + 2][arow] = av.z; As[akc + 3][arow] = av.w;
        float4 bv = *(const float4*)&W[(size_t)(k0 + brow) * (3 * CEMB) + n0 + bcol];
        *(float4*)&Bs[brow][bcol] = bv;
        __syncthreads();
#pragma unroll
        for (int k = 0; k < 8; k++) {
            float a[8], b[8];
            *(float4*)&a[0] = *(const float4*)&As[k][ty * 8];
            *(float4*)&a[4] = *(const float4*)&As[k][ty * 8 + 4];
            *(float4*)&b[0] = *(const float4*)&Bs[k][tx * 8];
            *(float4*)&b[4] = *(const float4*)&Bs[k][tx * 8 + 4];
#pragma unroll
            for (int i = 0; i < 8; i++)
#pragma unroll
                for (int j = 0; j < 8; j++)
                    acc[i][j] = fmaf(a[i], b[j], acc[i][j]);
        }
        __syncthreads();
    }

    // scatter epilogue: column n -> (which, head, d), row m -> (batch, t)
#pragma unroll
    for (int i = 0; i < 8; i++) {
        int m = m0 + ty * 8 + i;
        if (m >= MROWS) continue;
        int bb = m / TSEQ;
        int t  = m - bb * TSEQ;
#pragma unroll
        for (int j = 0; j < 8; j++) {
            int n = n0 + tx * 8 + j;
            int which = n / CEMB;
            int rem = n - which * CEMB;
            int h = rem >> 6;
            int d = rem & 63;
            float* dst = (which == 0) ? g_q : (which == 1) ? g_k : g_v;
            dst[((((size_t)bb * NHEAD + h) * TSEQ + t) << 6) + d] = acc[i][j];
        }
    }
}

// ---------------------------------------------------------------------------
// Output projection: g_y [6820 x 768] @ W_proj [768 x 768] -> d_out
// ---------------------------------------------------------------------------
__global__ __launch_bounds__(256) void proj_gemm(const float* __restrict__ W,
                                                 float* __restrict__ out) {
    __shared__ __align__(16) float As[8][136];
    __shared__ __align__(16) float Bs[8][136];
    const int m0 = blockIdx.y * 128;
    const int n0 = blockIdx.x * 128;
    const int tid = threadIdx.x;
    const int ty = tid >> 4;
    const int tx = tid & 15;

    float acc[8][8];
#pragma unroll
    for (int i = 0; i < 8; i++)
#pragma unroll
        for (int j = 0; j < 8; j++) acc[i][j] = 0.f;

    const int arow = tid >> 1;
    const int akc  = (tid & 1) * 4;
    const int brow = tid >> 5;
    const int bcol = (tid & 31) * 4;
    const int am   = m0 + arow;

    for (int k0 = 0; k0 < CEMB; k0 += 8) {
        float4 av = make_float4(0.f, 0.f, 0.f, 0.f);
        if (am < MROWS)
            av = *(const float4*)&g_y[(size_t)am * CEMB + k0 + akc];
        As[akc + 0][arow] = av.x; As[akc + 1][arow] = av.y;
        As[akc + 2][arow] = av.z; As[akc + 3][arow] = av.w;
        float4 bv = *(const float4*)&W[(size_t)(k0 + brow) * CEMB + n0 + bcol];
        *(float4*)&Bs[brow][bcol] = bv;
        __syncthreads();
#pragma unroll
        for (int k = 0; k < 8; k++) {
            float a[8], b[8];
            *(float4*)&a[0] = *(const float4*)&As[k][ty * 8];
            *(float4*)&a[4] = *(const float4*)&As[k][ty * 8 + 4];
            *(float4*)&b[0] = *(const float4*)&Bs[k][tx * 8];
            *(float4*)&b[4] = *(const float4*)&Bs[k][tx * 8 + 4];
#pragma unroll
            for (int i = 0; i < 8; i++)
#pragma unroll
                for (int j = 0; j < 8; j++)
                    acc[i][j] = fmaf(a[i], b[j], acc[i][j]);
        }
        __syncthreads();
    }

#pragma unroll
    for (int i = 0; i < 8; i++) {
        int m = m0 + ty * 8 + i;
        if (m >= MROWS) continue;
        *(float4*)&out[(size_t)m * CEMB + n0 + tx * 8]     = *(float4*)&acc[i][0];
        *(float4*)&out[(size_t)m * CEMB + n0 + tx * 8 + 4] = *(float4*)&acc[i][4];
    }
}

// ---------------------------------------------------------------------------
// Flash attention (fp32, single pass, online softmax, mask-tile skipping)
// One block per (q-tile 64, head, batch). 256 threads, 4x4 micro-tiles.
// Masked probabilities are explicitly zeroed (never rely on exp(-big)).
// ---------------------------------------------------------------------------
__global__ __launch_bounds__(256) void attn_kernel() {
    extern __shared__ float sm[];
    float* Qt      = sm;                     // [64 d][72]  (Q transposed, pre-scaled)
    float* Kt      = Qt + 64 * 72;           // [64 d][72]  (K transposed)
    float* Vs      = Kt + 64 * 72;           // [64 key][72]
    float* Pt      = Vs + 64 * 72;           // [64 key][72] (P transposed)
    float* red     = Pt + 64 * 72;           // [64][16] reduction buffer
    float* m_run   = red + 64 * 16;          // [64]
    float* l_run   = m_run + 64;             // [64]
    float* alpha_s = l_run + 64;             // [64]
    float* mnew_s  = alpha_s + 64;           // [64]
    unsigned char* msk = (unsigned char*)(mnew_s + 64);  // [64*64]

    const int qt = blockIdx.x, h = blockIdx.y, b = blockIdx.z;
    const int q0 = qt * 64;
    const int tid = threadIdx.x;
    const int ty = tid >> 4, tx = tid & 15;
    const int r0 = ty * 4, c0 = tx * 4;
    const size_t bh = ((size_t)b * NHEAD + h) * TSEQ;

    // Load Q tile, scale by 1/sqrt(64), store transposed (d-major)
    for (int i = tid; i < 64 * 16; i += 256) {
        int row = i >> 4;
        int dc  = (i & 15) * 4;
        float4 v = make_float4(0.f, 0.f, 0.f, 0.f);
        int q = q0 + row;
        if (q < TSEQ) v = *(const float4*)&g_q[(bh + q) * 64 + dc];
        Qt[(dc + 0) * 72 + row] = v.x * 0.125f;
        Qt[(dc + 1) * 72 + row] = v.y * 0.125f;
        Qt[(dc + 2) * 72 + row] = v.z * 0.125f;
        Qt[(dc + 3) * 72 + row] = v.w * 0.125f;
    }
    if (tid < 64) { m_run[tid] = -1e30f; l_run[tid] = 0.f; }

    float o[4][4];
#pragma unroll
    for (int i = 0; i < 4; i++)
#pragma unroll
        for (int j = 0; j < 4; j++) o[i][j] = 0.f;
    __syncthreads();

    for (int kt = 0; kt < KTILES; kt++) {
        const int k0 = kt * 64;

        // Load mask tile; compute tile-any for skipping
        int localany = 0;
        for (int i = tid; i < 64 * 64; i += 256) {
            int row = i >> 6, col = i & 63;
            int q = q0 + row, kk = k0 + col;
            unsigned char mv = 0;
            if (q < TSEQ && kk < TSEQ) mv = g_mask[(size_t)q * TSEQ + kk];
            msk[i] = mv;
            localany |= mv;
        }
        if (!__syncthreads_or(localany)) continue;   // fully-masked tile: skip

        // Load K (transposed) and V tiles
        for (int i = tid; i < 64 * 16; i += 256) {
            int row = i >> 4;
            int dc  = (i & 15) * 4;
            int kk  = k0 + row;
            float4 kv = make_float4(0.f, 0.f, 0.f, 0.f);
            float4 vv = kv;
            if (kk < TSEQ) {
                kv = *(const float4*)&g_k[(bh + kk) * 64 + dc];
                vv = *(const float4*)&g_v[(bh + kk) * 64 + dc];
            }
            Kt[(dc + 0) * 72 + row] = kv.x;
            Kt[(dc + 1) * 72 + row] = kv.y;
            Kt[(dc + 2) * 72 + row] = kv.z;
            Kt[(dc + 3) * 72 + row] = kv.w;
            *(float4*)&Vs[row * 72 + dc] = vv;
        }
        __syncthreads();

        // S = Q·K^T (4x4 per thread, in registers)
        float s[4][4];
#pragma unroll
        for (int i = 0; i < 4; i++)
#pragma unroll
            for (int j = 0; j < 4; j++) s[i][j] = 0.f;
#pragma unroll 8
        for (int d = 0; d < 64; d++) {
            float4 a = *(const float4*)&Qt[d * 72 + r0];
            float4 bb = *(const float4*)&Kt[d * 72 + c0];
            float av[4] = {a.x, a.y, a.z, a.w};
            float bv[4] = {bb.x, bb.y, bb.z, bb.w};
#pragma unroll
            for (int i = 0; i < 4; i++)
#pragma unroll
                for (int j = 0; j < 4; j++)
                    s[i][j] = fmaf(av[i], bv[j], s[i][j]);
        }

        // Per-thread mask bits (as float multipliers) + partial row max
        float mbit[4][4];
#pragma unroll
        for (int i = 0; i < 4; i++) {
            float pm = -1e30f;
#pragma unroll
            for (int j = 0; j < 4; j++) {
                float mb = msk[(r0 + i) * 64 + (c0 + j)] ? 1.0f : 0.0f;
                mbit[i][j] = mb;
                // masked entries contribute -1e30 to the max
                float sv = mb != 0.0f ? s[i][j] : -1e30f;
                s[i][j] = sv;
                pm = fmaxf(pm, sv);
            }
            red[(r0 + i) * 16 + tx] = pm;
        }
        __syncthreads();

        if (tid < 64) {
            float tm = red[tid * 16];
#pragma unroll
            for (int j = 1; j < 16; j++) tm = fmaxf(tm, red[tid * 16 + j]);
            float mo = m_run[tid];
            float mn = fmaxf(mo, tm);
            m_run[tid]   = mn;
            mnew_s[tid]  = mn;
            alpha_s[tid] = __expf(mo - mn);   // mo==mn==-1e30 -> exp(0)=1, harmless (o=0,l=0)
        }
        __syncthreads();

        // P = mask * exp(S - m_new) (store transposed), partial row sums, rescale O
#pragma unroll
        for (int i = 0; i < 4; i++) {
            float mn = mnew_s[r0 + i];
            float al = alpha_s[r0 + i];
            float ps = 0.f;
#pragma unroll
            for (int j = 0; j < 4; j++) {
                // explicit zero for masked entries: immune to m_new degeneracy
                float p = mbit[i][j] * __expf(s[i][j] - mn);
                ps += p;
                Pt[(c0 + j) * 72 + (r0 + i)] = p;
            }
            red[(r0 + i) * 16 + tx] = ps;
#pragma unroll
            for (int j = 0; j < 4; j++) o[i][j] *= al;
        }
        __syncthreads();

        if (tid < 64) {
            float ls = 0.f;
#pragma unroll
            for (int j = 0; j < 16; j++) ls += red[tid * 16 + j];
            l_run[tid] = l_run[tid] * alpha_s[tid] + ls;
        }

        // O += P·V
#pragma unroll 8
        for (int kk = 0; kk < 64; kk++) {
            float4 a = *(const float4*)&Pt[kk * 72 + r0];
            float4 v = *(const float4*)&Vs[kk * 72 + c0];
            float av[4] = {a.x, a.y, a.z, a.w};
            float vv[4] = {v.x, v.y, v.z, v.w};
#pragma unroll
            for (int i = 0; i < 4; i++)
#pragma unroll
                for (int j = 0; j < 4; j++)
                    o[i][j] = fmaf(av[i], vv[j], o[i][j]);
        }
        __syncthreads();
    }

    // Epilogue: normalize and write y[b, q, h*64 + d]
#pragma unroll
    for (int i = 0; i < 4; i++) {
        int q = q0 + r0 + i;
        if (q >= TSEQ) continue;
        float l = l_run[r0 + i];
        float inv = l > 0.f ? 1.0f / l : 0.f;
        float4 ov;
        ov.x = o[i][0] * inv; ov.y = o[i][1] * inv;
        ov.z = o[i][2] * inv; ov.w = o[i][3] * inv;
        *(float4*)&g_y[((size_t)b * TSEQ + q) * CEMB + h * 64 + c0] = ov;
    }
}

// ---------------------------------------------------------------------------
extern "C" void kernel_launch(void* const* d_in, const int* in_sizes, int n_in,
                              void* d_out, int out_size) {
    const float* x  = (const float*)d_in[0];
    const float* Wa = (const float*)d_in[1];
    const float* Wp = (const float*)d_in[2];
    const unsigned char* mask_raw = (const unsigned char*)d_in[3];
    float* out = (float*)d_out;

    // attention dynamic shared mem: 4 tiles [64][72] + red + stats + mask bytes
    const int SHBYTES = (4 * 64 * 72 + 64 * 16 + 4 * 64) * 4 + 64 * 64;  // 82944
    cudaFuncSetAttribute(attn_kernel, cudaFuncAttributeMaxDynamicSharedMemorySize, SHBYTES);

    {
        size_t n = (size_t)TSEQ * TSEQ;
        int blocks = (int)((n + 255) / 256);
        mask_convert<<<blocks, 256>>>(mask_raw);
    }

    dim3 g1(3 * CEMB / 128, (MROWS + 127) / 128);   // (18, 54)
    qkv_gemm<<<g1, 256>>>(x, Wa);

    dim3 g2(KTILES, NHEAD, BATCH);                  // (27, 12, 4)
    attn_kernel<<<g2, 256, SHBYTES>>>();

    dim3 g3(CEMB / 128, (MROWS + 127) / 128);       // (6, 54)
    proj_gemm<<<g3, 256>>>(Wp, out);
}

// round 4
// speedup vs baseline: 1.4139x; 1.4139x over previous
#include <cuda_runtime.h>
#include <math.h>

#define BATCH 4
#define TSEQ  1705
#define CEMB  768
#define NHEAD 12
#define HDIM  64
#define MROWS (BATCH*TSEQ)          /* 6820 */
#define KTILES ((TSEQ+63)/64)       /* 27   */
#define SA 136                      /* smem stride: 136%32==8 -> conflict-free frags */

// Scratch (static device arrays — no runtime allocation)
__device__ float g_q[(size_t)BATCH*NHEAD*TSEQ*HDIM];
__device__ float g_k[(size_t)BATCH*NHEAD*TSEQ*HDIM];
__device__ float g_v[(size_t)BATCH*NHEAD*TSEQ*HDIM];
__device__ float g_y[(size_t)MROWS*CEMB];
__device__ unsigned char g_mask[(size_t)TSEQ*TSEQ];

// ---------------------------------------------------------------------------
// Mask normalization (dtype sniff: mask[0,0]=1, mask[0,1]=1, mask[0,2]=0)
// ---------------------------------------------------------------------------
__global__ void mask_convert(const unsigned char* __restrict__ raw) {
    size_t i = (size_t)blockIdx.x * blockDim.x + threadIdx.x;
    if (i >= (size_t)TSEQ * TSEQ) return;
    unsigned char b0 = raw[0], b1 = raw[1];
    unsigned char v;
    if (b1 == 1)       v = raw[i] ? 1 : 0;              // uint8 / bool
    else if (b0 == 1)  v = ((const int*)raw)[i] != 0;   // int32
    else               v = ((const float*)raw)[i] != 0.0f; // float32
    g_mask[i] = v;
}

// ---------------------------------------------------------------------------
// tf32 helpers
// ---------------------------------------------------------------------------
__device__ __forceinline__ unsigned f2tf32(float x) {
    unsigned r;
    asm("cvt.rna.tf32.f32 %0, %1;" : "=r"(r) : "f"(x));
    return r;
}
__device__ __forceinline__ void mma_tf32(float* c, const unsigned* a, const unsigned* b) {
    asm volatile(
        "mma.sync.aligned.m16n8k8.row.col.f32.tf32.tf32.f32 "
        "{%0,%1,%2,%3}, {%4,%5,%6,%7}, {%8,%9}, {%0,%1,%2,%3};"
        : "+f"(c[0]), "+f"(c[1]), "+f"(c[2]), "+f"(c[3])
        : "r"(a[0]), "r"(a[1]), "r"(a[2]), "r"(a[3]), "r"(b[0]), "r"(b[1]));
}

// ---------------------------------------------------------------------------
// tf32 tensor-core GEMM: [MROWS x 768] @ [768 x LDB slice] (128x128x16 tiles)
// SCATTER=true  -> qkv: A = x (kernel arg), scatter into g_q/g_k/g_v
// SCATTER=false -> proj: A = g_y (device symbol, resolved IN DEVICE CODE),
//                  coalesced float2 stores to `out`
// ---------------------------------------------------------------------------
template<int LDB, bool SCATTER>
__global__ __launch_bounds__(256) void gemm_tf32(const float* __restrict__ Aarg,
                                                 const float* __restrict__ W,
                                                 float* __restrict__ out) {
    // CRITICAL: __device__ symbols must be resolved in device code, never
    // passed as kernel args from host (host shadow VA reads zeros via ATS).
    const float* __restrict__ A = SCATTER ? Aarg : (const float*)g_y;

    __shared__ unsigned As[2][16][SA];
    __shared__ unsigned Bs[2][16][SA];
    const int m0 = blockIdx.y * 128;
    const int n0 = blockIdx.x * 128;
    const int tid = threadIdx.x;
    const int lane = tid & 31;
    const int warp = tid >> 5;
    const int wm = (warp & 3) * 32;   // 4 warp-rows of 32
    const int wn = (warp >> 2) * 64;  // 2 warp-cols of 64

    float acc[2][8][4];
#pragma unroll
    for (int mf = 0; mf < 2; mf++)
#pragma unroll
        for (int nf = 0; nf < 8; nf++)
#pragma unroll
            for (int r = 0; r < 4; r++) acc[mf][nf][r] = 0.f;

    float4 aS[2], bS[2];

    // per-thread load coords (A: transpose to [k][m]; B: direct [k][n])
    const int a_m[2]  = { (tid + 0) >> 2, (tid + 256) >> 2 };
    const int a_kq    = (tid & 3) * 4;
    const int b_r[2]  = { (tid + 0) >> 5, (tid + 256) >> 5 };
    const int b_c     = (tid & 31) * 4;

#define LOAD_TILE(kt)                                                          \
    {                                                                          \
        int k0 = (kt) * 16;                                                    \
        _Pragma("unroll")                                                      \
        for (int u = 0; u < 2; u++) {                                          \
            int gm = m0 + a_m[u];                                              \
            aS[u] = make_float4(0.f, 0.f, 0.f, 0.f);                           \
            if (gm < MROWS)                                                    \
                aS[u] = *(const float4*)&A[(size_t)gm * 768 + k0 + a_kq];      \
            bS[u] = *(const float4*)&W[(size_t)(k0 + b_r[u]) * LDB + n0 + b_c];\
        }                                                                      \
    }

#define STORE_TILE(buf)                                                        \
    {                                                                          \
        _Pragma("unroll")                                                      \
        for (int u = 0; u < 2; u++) {                                          \
            As[buf][a_kq + 0][a_m[u]] = f2tf32(aS[u].x);                       \
            As[buf][a_kq + 1][a_m[u]] = f2tf32(aS[u].y);                       \
            As[buf][a_kq + 2][a_m[u]] = f2tf32(aS[u].z);                       \
            As[buf][a_kq + 3][a_m[u]] = f2tf32(aS[u].w);                       \
            unsigned* bp = &Bs[buf][b_r[u]][b_c];                              \
            bp[0] = f2tf32(bS[u].x); bp[1] = f2tf32(bS[u].y);                  \
            bp[2] = f2tf32(bS[u].z); bp[3] = f2tf32(bS[u].w);                  \
        }                                                                      \
    }

    LOAD_TILE(0);
    STORE_TILE(0);
    __syncthreads();

    const int NK = 768 / 16;  // 48
    for (int kt = 0; kt < NK; kt++) {
        const int cur = kt & 1;
        if (kt + 1 < NK) LOAD_TILE(kt + 1);

#pragma unroll
        for (int ks = 0; ks < 2; ks++) {
            const int kb = ks * 8;
            unsigned af[2][4], bf[8][2];
            const int fr = lane >> 2;   // frag row/col component
            const int fc = lane & 3;    // frag k component
#pragma unroll
            for (int mf = 0; mf < 2; mf++) {
                af[mf][0] = As[cur][kb + fc][wm + mf * 16 + fr];
                af[mf][1] = As[cur][kb + fc][wm + mf * 16 + fr + 8];
                af[mf][2] = As[cur][kb + fc + 4][wm + mf * 16 + fr];
                af[mf][3] = As[cur][kb + fc + 4][wm + mf * 16 + fr + 8];
            }
#pragma unroll
            for (int nf = 0; nf < 8; nf++) {
                bf[nf][0] = Bs[cur][kb + fc][wn + nf * 8 + fr];
                bf[nf][1] = Bs[cur][kb + fc + 4][wn + nf * 8 + fr];
            }
#pragma unroll
            for (int mf = 0; mf < 2; mf++)
#pragma unroll
                for (int nf = 0; nf < 8; nf++)
                    mma_tf32(acc[mf][nf], af[mf], bf[nf]);
        }

        if (kt + 1 < NK) STORE_TILE(cur ^ 1);
        __syncthreads();
    }

    // Epilogue
    if (SCATTER) {
#pragma unroll
        for (int mf = 0; mf < 2; mf++)
#pragma unroll
            for (int nf = 0; nf < 8; nf++)
#pragma unroll
                for (int rg = 0; rg < 4; rg++) {
                    int m = m0 + wm + mf * 16 + (lane >> 2) + ((rg >= 2) ? 8 : 0);
                    if (m >= MROWS) continue;
                    int n = n0 + wn + nf * 8 + 2 * (lane & 3) + (rg & 1);
                    int bb = m / TSEQ;
                    int t  = m - bb * TSEQ;
                    int which = n / CEMB;
                    int rem = n - which * CEMB;
                    int h = rem >> 6, d = rem & 63;
                    float* dst = (which == 0) ? g_q : (which == 1) ? g_k : g_v;
                    dst[((((size_t)bb * NHEAD + h) * TSEQ + t) << 6) + d] = acc[mf][nf][rg];
                }
    } else {
#pragma unroll
        for (int mf = 0; mf < 2; mf++)
#pragma unroll
            for (int nf = 0; nf < 8; nf++) {
                int n  = n0 + wn + nf * 8 + 2 * (lane & 3);
                int m1 = m0 + wm + mf * 16 + (lane >> 2);
                if (m1 < MROWS)
                    *(float2*)&out[(size_t)m1 * CEMB + n] =
                        make_float2(acc[mf][nf][0], acc[mf][nf][1]);
                int m2 = m1 + 8;
                if (m2 < MROWS)
                    *(float2*)&out[(size_t)m2 * CEMB + n] =
                        make_float2(acc[mf][nf][2], acc[mf][nf][3]);
            }
    }
#undef LOAD_TILE
#undef STORE_TILE
}

// ---------------------------------------------------------------------------
// Flash attention (fp32, single pass, online softmax, mask-tile skipping)
// One block per (q-tile 64, head, batch). 256 threads, 4x4 micro-tiles.
// ---------------------------------------------------------------------------
__global__ __launch_bounds__(256) void attn_kernel() {
    extern __shared__ float sm[];
    float* Qt      = sm;                     // [64 d][72]
    float* Kt      = Qt + 64 * 72;           // [64 d][72]
    float* Vs      = Kt + 64 * 72;           // [64 key][72]
    float* Pt      = Vs + 64 * 72;           // [64 key][72]
    float* red     = Pt + 64 * 72;           // [64][16]
    float* m_run   = red + 64 * 16;
    float* l_run   = m_run + 64;
    float* alpha_s = l_run + 64;
    float* mnew_s  = alpha_s + 64;
    unsigned char* msk = (unsigned char*)(mnew_s + 64);  // [64*64]

    const int qt = blockIdx.x, h = blockIdx.y, b = blockIdx.z;
    const int q0 = qt * 64;
    const int tid = threadIdx.x;
    const int ty = tid >> 4, tx = tid & 15;
    const int r0 = ty * 4, c0 = tx * 4;
    const size_t bh = ((size_t)b * NHEAD + h) * TSEQ;

    for (int i = tid; i < 64 * 16; i += 256) {
        int row = i >> 4;
        int dc  = (i & 15) * 4;
        float4 v = make_float4(0.f, 0.f, 0.f, 0.f);
        int q = q0 + row;
        if (q < TSEQ) v = *(const float4*)&g_q[(bh + q) * 64 + dc];
        Qt[(dc + 0) * 72 + row] = v.x * 0.125f;
        Qt[(dc + 1) * 72 + row] = v.y * 0.125f;
        Qt[(dc + 2) * 72 + row] = v.z * 0.125f;
        Qt[(dc + 3) * 72 + row] = v.w * 0.125f;
    }
    if (tid < 64) { m_run[tid] = -1e30f; l_run[tid] = 0.f; }

    float o[4][4];
#pragma unroll
    for (int i = 0; i < 4; i++)
#pragma unroll
        for (int j = 0; j < 4; j++) o[i][j] = 0.f;
    __syncthreads();

    for (int kt = 0; kt < KTILES; kt++) {
        const int k0 = kt * 64;

        int localany = 0;
        for (int i = tid; i < 64 * 64; i += 256) {
            int row = i >> 6, col = i & 63;
            int q = q0 + row, kk = k0 + col;
            unsigned char mv = 0;
            if (q < TSEQ && kk < TSEQ) mv = g_mask[(size_t)q * TSEQ + kk];
            msk[i] = mv;
            localany |= mv;
        }
        if (!__syncthreads_or(localany)) continue;

        for (int i = tid; i < 64 * 16; i += 256) {
            int row = i >> 4;
            int dc  = (i & 15) * 4;
            int kk  = k0 + row;
            float4 kv = make_float4(0.f, 0.f, 0.f, 0.f);
            float4 vv = kv;
            if (kk < TSEQ) {
                kv = *(const float4*)&g_k[(bh + kk) * 64 + dc];
                vv = *(const float4*)&g_v[(bh + kk) * 64 + dc];
            }
            Kt[(dc + 0) * 72 + row] = kv.x;
            Kt[(dc + 1) * 72 + row] = kv.y;
            Kt[(dc + 2) * 72 + row] = kv.z;
            Kt[(dc + 3) * 72 + row] = kv.w;
            *(float4*)&Vs[row * 72 + dc] = vv;
        }
        __syncthreads();

        float s[4][4];
#pragma unroll
        for (int i = 0; i < 4; i++)
#pragma unroll
            for (int j = 0; j < 4; j++) s[i][j] = 0.f;
#pragma unroll 8
        for (int d = 0; d < 64; d++) {
            float4 a = *(const float4*)&Qt[d * 72 + r0];
            float4 bb = *(const float4*)&Kt[d * 72 + c0];
            float av[4] = {a.x, a.y, a.z, a.w};
            float bv[4] = {bb.x, bb.y, bb.z, bb.w};
#pragma unroll
            for (int i = 0; i < 4; i++)
#pragma unroll
                for (int j = 0; j < 4; j++)
                    s[i][j] = fmaf(av[i], bv[j], s[i][j]);
        }

        float mbit[4][4];
#pragma unroll
        for (int i = 0; i < 4; i++) {
            float pm = -1e30f;
#pragma unroll
            for (int j = 0; j < 4; j++) {
                float mb = msk[(r0 + i) * 64 + (c0 + j)] ? 1.0f : 0.0f;
                mbit[i][j] = mb;
                float sv = mb != 0.0f ? s[i][j] : -1e30f;
                s[i][j] = sv;
                pm = fmaxf(pm, sv);
            }
            red[(r0 + i) * 16 + tx] = pm;
        }
        __syncthreads();

        if (tid < 64) {
            float tm = red[tid * 16];
#pragma unroll
            for (int j = 1; j < 16; j++) tm = fmaxf(tm, red[tid * 16 + j]);
            float mo = m_run[tid];
            float mn = fmaxf(mo, tm);
            m_run[tid]   = mn;
            mnew_s[tid]  = mn;
            alpha_s[tid] = __expf(mo - mn);
        }
        __syncthreads();

#pragma unroll
        for (int i = 0; i < 4; i++) {
            float mn = mnew_s[r0 + i];
            float al = alpha_s[r0 + i];
            float ps = 0.f;
#pragma unroll
            for (int j = 0; j < 4; j++) {
                float p = mbit[i][j] * __expf(s[i][j] - mn);
                ps += p;
                Pt[(c0 + j) * 72 + (r0 + i)] = p;
            }
            red[(r0 + i) * 16 + tx] = ps;
#pragma unroll
            for (int j = 0; j < 4; j++) o[i][j] *= al;
        }
        __syncthreads();

        if (tid < 64) {
            float ls = 0.f;
#pragma unroll
            for (int j = 0; j < 16; j++) ls += red[tid * 16 + j];
            l_run[tid] = l_run[tid] * alpha_s[tid] + ls;
        }

#pragma unroll 8
        for (int kk = 0; kk < 64; kk++) {
            float4 a = *(const float4*)&Pt[kk * 72 + r0];
            float4 v = *(const float4*)&Vs[kk * 72 + c0];
            float av[4] = {a.x, a.y, a.z, a.w};
            float vv[4] = {v.x, v.y, v.z, v.w};
#pragma unroll
            for (int i = 0; i < 4; i++)
#pragma unroll
                for (int j = 0; j < 4; j++)
                    o[i][j] = fmaf(av[i], vv[j], o[i][j]);
        }
        __syncthreads();
    }

#pragma unroll
    for (int i = 0; i < 4; i++) {
        int q = q0 + r0 + i;
        if (q >= TSEQ) continue;
        float l = l_run[r0 + i];
        float inv = l > 0.f ? 1.0f / l : 0.f;
        float4 ov;
        ov.x = o[i][0] * inv; ov.y = o[i][1] * inv;
        ov.z = o[i][2] * inv; ov.w = o[i][3] * inv;
        *(float4*)&g_y[((size_t)b * TSEQ + q) * CEMB + h * 64 + c0] = ov;
    }
}

// ---------------------------------------------------------------------------
extern "C" void kernel_launch(void* const* d_in, const int* in_sizes, int n_in,
                              void* d_out, int out_size) {
    const float* x  = (const float*)d_in[0];
    const float* Wa = (const float*)d_in[1];
    const float* Wp = (const float*)d_in[2];
    const unsigned char* mask_raw = (const unsigned char*)d_in[3];
    float* out = (float*)d_out;

    const int SHBYTES = (4 * 64 * 72 + 64 * 16 + 4 * 64) * 4 + 64 * 64;  // 82944
    cudaFuncSetAttribute(attn_kernel, cudaFuncAttributeMaxDynamicSharedMemorySize, SHBYTES);

    {
        size_t n = (size_t)TSEQ * TSEQ;
        mask_convert<<<(int)((n + 255) / 256), 256>>>(mask_raw);
    }

    dim3 g1(3 * CEMB / 128, (MROWS + 127) / 128);   // (18, 54)
    gemm_tf32<3 * CEMB, true><<<g1, 256>>>(x, Wa, nullptr);

    dim3 g2(KTILES, NHEAD, BATCH);                  // (27, 12, 4)
    attn_kernel<<<g2, 256, SHBYTES>>>();

    dim3 g3(CEMB / 128, (MROWS + 127) / 128);       // (6, 54)
    gemm_tf32<CEMB, false><<<g3, 256>>>(nullptr, Wp, out);   // A = g_y (in-device)
}

// round 5
// speedup vs baseline: 2.6760x; 1.8926x over previous
#include <cuda_runtime.h>
#include <math.h>

#define BATCH 4
#define TSEQ  1705
#define CEMB  768
#define NHEAD 12
#define HDIM  64
#define MROWS (BATCH*TSEQ)          /* 6820 */
#define KTILES ((TSEQ+63)/64)       /* 27   */
#define SA 136                      /* gemm smem stride */
#define SK 68                       /* attn smem stride: bank = 4*fr+fc, conflict-free */

// Scratch (static device arrays — no runtime allocation)
__device__ float g_q[(size_t)BATCH*NHEAD*TSEQ*HDIM];
__device__ float g_k[(size_t)BATCH*NHEAD*TSEQ*HDIM];
__device__ float g_v[(size_t)BATCH*NHEAD*TSEQ*HDIM];
__device__ float g_y[(size_t)MROWS*CEMB];
__device__ unsigned char g_mask[(size_t)TSEQ*TSEQ];

// ---------------------------------------------------------------------------
// Mask normalization (dtype sniff: mask[0,0]=1, mask[0,1]=1, mask[0,2]=0)
// ---------------------------------------------------------------------------
__global__ void mask_convert(const unsigned char* __restrict__ raw) {
    size_t i = (size_t)blockIdx.x * blockDim.x + threadIdx.x;
    if (i >= (size_t)TSEQ * TSEQ) return;
    unsigned char b0 = raw[0], b1 = raw[1];
    unsigned char v;
    if (b1 == 1)       v = raw[i] ? 1 : 0;
    else if (b0 == 1)  v = ((const int*)raw)[i] != 0;
    else               v = ((const float*)raw)[i] != 0.0f;
    g_mask[i] = v;
}

// ---------------------------------------------------------------------------
// tf32 helpers
// ---------------------------------------------------------------------------
__device__ __forceinline__ unsigned f2tf32(float x) {
    unsigned r;
    asm("cvt.rna.tf32.f32 %0, %1;" : "=r"(r) : "f"(x));
    return r;
}
__device__ __forceinline__ void mma_tf32(float* c, const unsigned* a, const unsigned* b) {
    asm volatile(
        "mma.sync.aligned.m16n8k8.row.col.f32.tf32.tf32.f32 "
        "{%0,%1,%2,%3}, {%4,%5,%6,%7}, {%8,%9}, {%0,%1,%2,%3};"
        : "+f"(c[0]), "+f"(c[1]), "+f"(c[2]), "+f"(c[3])
        : "r"(a[0]), "r"(a[1]), "r"(a[2]), "r"(a[3]), "r"(b[0]), "r"(b[1]));
}

// ---------------------------------------------------------------------------
// tf32 tensor-core GEMM (unchanged from R4 — known good)
// ---------------------------------------------------------------------------
template<int LDB, bool SCATTER>
__global__ __launch_bounds__(256) void gemm_tf32(const float* __restrict__ Aarg,
                                                 const float* __restrict__ W,
                                                 float* __restrict__ out) {
    const float* __restrict__ A = SCATTER ? Aarg : (const float*)g_y;

    __shared__ unsigned As[2][16][SA];
    __shared__ unsigned Bs[2][16][SA];
    const int m0 = blockIdx.y * 128;
    const int n0 = blockIdx.x * 128;
    const int tid = threadIdx.x;
    const int lane = tid & 31;
    const int warp = tid >> 5;
    const int wm = (warp & 3) * 32;
    const int wn = (warp >> 2) * 64;

    float acc[2][8][4];
#pragma unroll
    for (int mf = 0; mf < 2; mf++)
#pragma unroll
        for (int nf = 0; nf < 8; nf++)
#pragma unroll
            for (int r = 0; r < 4; r++) acc[mf][nf][r] = 0.f;

    float4 aS[2], bS[2];
    const int a_m[2]  = { (tid + 0) >> 2, (tid + 256) >> 2 };
    const int a_kq    = (tid & 3) * 4;
    const int b_r[2]  = { (tid + 0) >> 5, (tid + 256) >> 5 };
    const int b_c     = (tid & 31) * 4;

#define LOAD_TILE(kt)                                                          \
    {                                                                          \
        int k0 = (kt) * 16;                                                    \
        _Pragma("unroll")                                                      \
        for (int u = 0; u < 2; u++) {                                          \
            int gm = m0 + a_m[u];                                              \
            aS[u] = make_float4(0.f, 0.f, 0.f, 0.f);                           \
            if (gm < MROWS)                                                    \
                aS[u] = *(const float4*)&A[(size_t)gm * 768 + k0 + a_kq];      \
            bS[u] = *(const float4*)&W[(size_t)(k0 + b_r[u]) * LDB + n0 + b_c];\
        }                                                                      \
    }

#define STORE_TILE(buf)                                                        \
    {                                                                          \
        _Pragma("unroll")                                                      \
        for (int u = 0; u < 2; u++) {                                          \
            As[buf][a_kq + 0][a_m[u]] = f2tf32(aS[u].x);                       \
            As[buf][a_kq + 1][a_m[u]] = f2tf32(aS[u].y);                       \
            As[buf][a_kq + 2][a_m[u]] = f2tf32(aS[u].z);                       \
            As[buf][a_kq + 3][a_m[u]] = f2tf32(aS[u].w);                       \
            unsigned* bp = &Bs[buf][b_r[u]][b_c];                              \
            bp[0] = f2tf32(bS[u].x); bp[1] = f2tf32(bS[u].y);                  \
            bp[2] = f2tf32(bS[u].z); bp[3] = f2tf32(bS[u].w);                  \
        }                                                                      \
    }

    LOAD_TILE(0);
    STORE_TILE(0);
    __syncthreads();

    const int NK = 768 / 16;
    for (int kt = 0; kt < NK; kt++) {
        const int cur = kt & 1;
        if (kt + 1 < NK) LOAD_TILE(kt + 1);

#pragma unroll
        for (int ks = 0; ks < 2; ks++) {
            const int kb = ks * 8;
            unsigned af[2][4], bf[8][2];
            const int fr = lane >> 2;
            const int fc = lane & 3;
#pragma unroll
            for (int mf = 0; mf < 2; mf++) {
                af[mf][0] = As[cur][kb + fc][wm + mf * 16 + fr];
                af[mf][1] = As[cur][kb + fc][wm + mf * 16 + fr + 8];
                af[mf][2] = As[cur][kb + fc + 4][wm + mf * 16 + fr];
                af[mf][3] = As[cur][kb + fc + 4][wm + mf * 16 + fr + 8];
            }
#pragma unroll
            for (int nf = 0; nf < 8; nf++) {
                bf[nf][0] = Bs[cur][kb + fc][wn + nf * 8 + fr];
                bf[nf][1] = Bs[cur][kb + fc + 4][wn + nf * 8 + fr];
            }
#pragma unroll
            for (int mf = 0; mf < 2; mf++)
#pragma unroll
                for (int nf = 0; nf < 8; nf++)
                    mma_tf32(acc[mf][nf], af[mf], bf[nf]);
        }

        if (kt + 1 < NK) STORE_TILE(cur ^ 1);
        __syncthreads();
    }

    if (SCATTER) {
#pragma unroll
        for (int mf = 0; mf < 2; mf++)
#pragma unroll
            for (int nf = 0; nf < 8; nf++)
#pragma unroll
                for (int rg = 0; rg < 4; rg++) {
                    int m = m0 + wm + mf * 16 + (lane >> 2) + ((rg >= 2) ? 8 : 0);
                    if (m >= MROWS) continue;
                    int n = n0 + wn + nf * 8 + 2 * (lane & 3) + (rg & 1);
                    int bb = m / TSEQ;
                    int t  = m - bb * TSEQ;
                    int which = n / CEMB;
                    int rem = n - which * CEMB;
                    int h = rem >> 6, d = rem & 63;
                    float* dst = (which == 0) ? g_q : (which == 1) ? g_k : g_v;
                    dst[((((size_t)bb * NHEAD + h) * TSEQ + t) << 6) + d] = acc[mf][nf][rg];
                }
    } else {
#pragma unroll
        for (int mf = 0; mf < 2; mf++)
#pragma unroll
            for (int nf = 0; nf < 8; nf++) {
                int n  = n0 + wn + nf * 8 + 2 * (lane & 3);
                int m1 = m0 + wm + mf * 16 + (lane >> 2);
                if (m1 < MROWS)
                    *(float2*)&out[(size_t)m1 * CEMB + n] =
                        make_float2(acc[mf][nf][0], acc[mf][nf][1]);
                int m2 = m1 + 8;
                if (m2 < MROWS)
                    *(float2*)&out[(size_t)m2 * CEMB + n] =
                        make_float2(acc[mf][nf][2], acc[mf][nf][3]);
            }
    }
#undef LOAD_TILE
#undef STORE_TILE
}

// ---------------------------------------------------------------------------
// Tensor-core flash attention (tf32 mma, fp32 softmax, mask-tile skipping)
// One block per (q-tile 64, head, batch). 8 warps as 4x2 over the 64x64 tile:
// warp = (wr, wc), owns S chunk rows [wr*16,+16) x cols [wc*32,+32).
// ---------------------------------------------------------------------------
__global__ __launch_bounds__(256) void attn_tc() {
    extern __shared__ float smf[];
    unsigned* Ks  = (unsigned*)smf;          // [64 key][SK] tf32 bits (B of S)
    unsigned* Vt  = Ks + 64 * SK;            // [64 d][SK]  tf32 bits (B of PV, V^T)
    unsigned* Ps  = Vt + 64 * SK;            // [64 q][SK]  tf32 bits (A of PV); Q staging
    float* red    = (float*)(Ps + 64 * SK);  // [64][8]
    float* m_run  = red + 64 * 8;
    float* l_run  = m_run + 64;
    float* alpha_s= l_run + 64;
    float* mnew_s = alpha_s + 64;
    unsigned char* msk = (unsigned char*)(mnew_s + 64);  // [64*64]

    const int qt = blockIdx.x, h = blockIdx.y, b = blockIdx.z;
    const int q0 = qt * 64;
    const int tid = threadIdx.x, lane = tid & 31, warp = tid >> 5;
    const int wr = warp & 3, wc = warp >> 2;
    const int wm = wr * 16, wn = wc * 32;
    const int fr = lane >> 2, fc = lane & 3;
    const size_t bh = ((size_t)b * NHEAD + h) * TSEQ;

    // Stage Q (scaled) through Ps as floats, then hoist Q fragments (loop-invariant)
    float* Qstage = (float*)Ps;
    for (int i = tid; i < 64 * 16; i += 256) {
        int row = i >> 4, dc = (i & 15) * 4;
        float4 v = make_float4(0.f, 0.f, 0.f, 0.f);
        int q = q0 + row;
        if (q < TSEQ) v = *(const float4*)&g_q[(bh + q) * 64 + dc];
        float* p = &Qstage[row * SK + dc];
        p[0] = v.x * 0.125f; p[1] = v.y * 0.125f;
        p[2] = v.z * 0.125f; p[3] = v.w * 0.125f;
    }
    if (tid < 64) { m_run[tid] = -1e30f; l_run[tid] = 0.f; }
    __syncthreads();

    unsigned qf[8][4];
#pragma unroll
    for (int ks = 0; ks < 8; ks++) {
        int kk = ks * 8;
        qf[ks][0] = f2tf32(Qstage[(wm + fr)     * SK + kk + fc]);
        qf[ks][1] = f2tf32(Qstage[(wm + fr + 8) * SK + kk + fc]);
        qf[ks][2] = f2tf32(Qstage[(wm + fr)     * SK + kk + fc + 4]);
        qf[ks][3] = f2tf32(Qstage[(wm + fr + 8) * SK + kk + fc + 4]);
    }
    __syncthreads();

    // O accumulators: [nf][c], rows (wm+fr, wm+fr+8), cols wn+nf*8+2fc{,+1}
    float o[4][4];
#pragma unroll
    for (int nf = 0; nf < 4; nf++)
#pragma unroll
        for (int r = 0; r < 4; r++) o[nf][r] = 0.f;

    for (int kt = 0; kt < KTILES; kt++) {
        const int k0 = kt * 64;

        // Mask tile + skip test
        int localany = 0;
        for (int i = tid; i < 64 * 64; i += 256) {
            int row = i >> 6, col = i & 63;
            int q = q0 + row, kk2 = k0 + col;
            unsigned char mv = 0;
            if (q < TSEQ && kk2 < TSEQ) mv = g_mask[(size_t)q * TSEQ + kk2];
            msk[i] = mv;
            localany |= mv;
        }
        if (!__syncthreads_or(localany)) continue;

        // Stage K direct (row-major = col-major B of S), V transposed (B of PV)
        for (int i = tid; i < 64 * 16; i += 256) {
            int row = i >> 4, dc = (i & 15) * 4;
            int kk2 = k0 + row;
            float4 kv = make_float4(0.f, 0.f, 0.f, 0.f), vv = kv;
            if (kk2 < TSEQ) {
                kv = *(const float4*)&g_k[(bh + kk2) * 64 + dc];
                vv = *(const float4*)&g_v[(bh + kk2) * 64 + dc];
            }
            unsigned* kp = &Ks[row * SK + dc];
            kp[0] = f2tf32(kv.x); kp[1] = f2tf32(kv.y);
            kp[2] = f2tf32(kv.z); kp[3] = f2tf32(kv.w);
            Vt[(dc + 0) * SK + row] = f2tf32(vv.x);
            Vt[(dc + 1) * SK + row] = f2tf32(vv.y);
            Vt[(dc + 2) * SK + row] = f2tf32(vv.z);
            Vt[(dc + 3) * SK + row] = f2tf32(vv.w);
        }
        __syncthreads();

        // S = Q*K^T via tensor cores
        float sacc[4][4];
#pragma unroll
        for (int nf = 0; nf < 4; nf++)
#pragma unroll
            for (int r = 0; r < 4; r++) sacc[nf][r] = 0.f;
#pragma unroll
        for (int ks = 0; ks < 8; ks++) {
            int kk = ks * 8;
#pragma unroll
            for (int nf = 0; nf < 4; nf++) {
                unsigned bf[2];
                bf[0] = Ks[(wn + nf * 8 + fr) * SK + kk + fc];
                bf[1] = Ks[(wn + nf * 8 + fr) * SK + kk + fc + 4];
                mma_tf32(sacc[nf], qf[ks], bf);
            }
        }

        // Mask + per-thread row maxima (rows ra=wm+fr, rb=wm+fr+8)
        float mb[4][4];
        float pma = -1e30f, pmb = -1e30f;
        const int ra = wm + fr, rb = wm + fr + 8;
#pragma unroll
        for (int nf = 0; nf < 4; nf++) {
            int ca = wn + nf * 8 + 2 * fc;
            mb[nf][0] = msk[ra * 64 + ca]     ? 1.f : 0.f;
            mb[nf][1] = msk[ra * 64 + ca + 1] ? 1.f : 0.f;
            mb[nf][2] = msk[rb * 64 + ca]     ? 1.f : 0.f;
            mb[nf][3] = msk[rb * 64 + ca + 1] ? 1.f : 0.f;
            sacc[nf][0] = mb[nf][0] != 0.f ? sacc[nf][0] : -1e30f;
            sacc[nf][1] = mb[nf][1] != 0.f ? sacc[nf][1] : -1e30f;
            sacc[nf][2] = mb[nf][2] != 0.f ? sacc[nf][2] : -1e30f;
            sacc[nf][3] = mb[nf][3] != 0.f ? sacc[nf][3] : -1e30f;
            pma = fmaxf(pma, fmaxf(sacc[nf][0], sacc[nf][1]));
            pmb = fmaxf(pmb, fmaxf(sacc[nf][2], sacc[nf][3]));
        }
        red[ra * 8 + wc * 4 + fc] = pma;
        red[rb * 8 + wc * 4 + fc] = pmb;
        __syncthreads();

        if (tid < 64) {
            float tm = red[tid * 8];
#pragma unroll
            for (int j = 1; j < 8; j++) tm = fmaxf(tm, red[tid * 8 + j]);
            float mo = m_run[tid];
            float mn = fmaxf(mo, tm);
            m_run[tid]   = mn;
            mnew_s[tid]  = mn;
            alpha_s[tid] = __expf(mo - mn);
        }
        __syncthreads();

        // P = mask * exp(S - mn); write tf32 bits to Ps; row sums; rescale O
        const float mna = mnew_s[ra], mnb = mnew_s[rb];
        const float ala = alpha_s[ra], alb = alpha_s[rb];
        float psa = 0.f, psb = 0.f;
#pragma unroll
        for (int nf = 0; nf < 4; nf++) {
            int ca = wn + nf * 8 + 2 * fc;
            float p0 = mb[nf][0] * __expf(sacc[nf][0] - mna);
            float p1 = mb[nf][1] * __expf(sacc[nf][1] - mna);
            float p2 = mb[nf][2] * __expf(sacc[nf][2] - mnb);
            float p3 = mb[nf][3] * __expf(sacc[nf][3] - mnb);
            psa += p0 + p1; psb += p2 + p3;
            Ps[ra * SK + ca]     = f2tf32(p0);
            Ps[ra * SK + ca + 1] = f2tf32(p1);
            Ps[rb * SK + ca]     = f2tf32(p2);
            Ps[rb * SK + ca + 1] = f2tf32(p3);
            o[nf][0] *= ala; o[nf][1] *= ala;
            o[nf][2] *= alb; o[nf][3] *= alb;
        }
        red[ra * 8 + wc * 4 + fc] = psa;
        red[rb * 8 + wc * 4 + fc] = psb;
        __syncthreads();

        if (tid < 64) {
            float ls = 0.f;
#pragma unroll
            for (int j = 0; j < 8; j++) ls += red[tid * 8 + j];
            l_run[tid] = l_run[tid] * alpha_s[tid] + ls;
        }

        // O += P*V via tensor cores (Ps visible after the sync above)
#pragma unroll
        for (int ks = 0; ks < 8; ks++) {
            int kk = ks * 8;
            unsigned pa[4];
            pa[0] = Ps[ra * SK + kk + fc];
            pa[1] = Ps[rb * SK + kk + fc];
            pa[2] = Ps[ra * SK + kk + fc + 4];
            pa[3] = Ps[rb * SK + kk + fc + 4];
#pragma unroll
            for (int nf = 0; nf < 4; nf++) {
                unsigned bf[2];
                bf[0] = Vt[(wn + nf * 8 + fr) * SK + kk + fc];
                bf[1] = Vt[(wn + nf * 8 + fr) * SK + kk + fc + 4];
                mma_tf32(o[nf], pa, bf);
            }
        }
        __syncthreads();   // protect Ks/Vt/Ps/msk before next tile
    }

    // Epilogue: normalize and write y[b, q, h*64 + d]
    const int ra = wm + fr, rb = wm + fr + 8;
    float la = l_run[ra], lb = l_run[rb];
    float inva = la > 0.f ? 1.f / la : 0.f;
    float invb = lb > 0.f ? 1.f / lb : 0.f;
    int qa = q0 + ra, qb = q0 + rb;
#pragma unroll
    for (int nf = 0; nf < 4; nf++) {
        int d = h * 64 + wn + nf * 8 + 2 * fc;
        if (qa < TSEQ)
            *(float2*)&g_y[((size_t)b * TSEQ + qa) * CEMB + d] =
                make_float2(o[nf][0] * inva, o[nf][1] * inva);
        if (qb < TSEQ)
            *(float2*)&g_y[((size_t)b * TSEQ + qb) * CEMB + d] =
                make_float2(o[nf][2] * invb, o[nf][3] * invb);
    }
}

// ---------------------------------------------------------------------------
extern "C" void kernel_launch(void* const* d_in, const int* in_sizes, int n_in,
                              void* d_out, int out_size) {
    const float* x  = (const float*)d_in[0];
    const float* Wa = (const float*)d_in[1];
    const float* Wp = (const float*)d_in[2];
    const unsigned char* mask_raw = (const unsigned char*)d_in[3];
    float* out = (float*)d_out;

    // attn smem: 3x[64][SK] u32 + red[64][8] + 4x[64] f32 + msk 4096 B
    const int SHBYTES = (3 * 64 * SK + 64 * 8 + 4 * 64) * 4 + 64 * 64;  // 59392
    cudaFuncSetAttribute(attn_tc, cudaFuncAttributeMaxDynamicSharedMemorySize, SHBYTES);

    {
        size_t n = (size_t)TSEQ * TSEQ;
        mask_convert<<<(int)((n + 255) / 256), 256>>>(mask_raw);
    }

    dim3 g1(3 * CEMB / 128, (MROWS + 127) / 128);   // (18, 54)
    gemm_tf32<3 * CEMB, true><<<g1, 256>>>(x, Wa, nullptr);

    dim3 g2(KTILES, NHEAD, BATCH);                  // (27, 12, 4)
    attn_tc<<<g2, 256, SHBYTES>>>();

    dim3 g3(CEMB / 128, (MROWS + 127) / 128);       // (6, 54)
    gemm_tf32<CEMB, false><<<g3, 256>>>(nullptr, Wp, out);  // A = g_y in-device
}